// round 15
// baseline (speedup 1.0000x reference)
#include <cuda_runtime.h>
#include <cuda_bf16.h>
#include <cstdint>

// RoPE2D encoder: output = [cos_2d (HW x 128) ; sin_2d (HW x 128)], fp32.
// H = W = 512, DIM = 128. Channels [0,64) depend only on x, [64,128) only on y.
// Final design: dual-emit (each warp computes cos AND sin rows from one
// sincosf set -> lowest issue/byte, throttle-robust) + SINGLE-WAVE persistent
// grid: 1024 blocks x 256 thr = 8192 warps, <= 1184 concurrent on 148 SMs,
// so zero wave transitions; each warp handles exactly 4 groups of 8 positions.
// Lane q = float4 chunk: q<16 x-half (rotates by f per row), q>=16 y-half
// (identity rotation). Streaming STG.128 at the ~6300 B/cyc LTS write cap.

#define RP_H 512
#define RP_W 512
#define RP_HW (RP_H * RP_W)
#define ROWS_PER_WARP 8
#define GROUPS_PER_WARP 4
#define NUM_WARPS 8192          // 1024 blocks x 8 warps

__global__ void __launch_bounds__(256) rope2d_fused(float4* __restrict__ out,
                                                    const float* __restrict__ inv_freq_x,
                                                    const float* __restrict__ inv_freq_y) {
    unsigned warp_in_block = threadIdx.x >> 5;
    unsigned q             = threadIdx.x & 31u;
    unsigned gw  = blockIdx.x * 8u + warp_in_block;   // 0..8191

    bool is_x = (q < 16u);

    // channels 4*(q mod 16)+j ; freq index mod 32 -> aligned float4 at q&7.
    const float4* tf = reinterpret_cast<const float4*>(is_x ? inv_freq_x : inv_freq_y);
    float4 f4 = __ldg(tf + (q & 7u));
    float fr[4] = {f4.x, f4.y, f4.z, f4.w};

    float step = is_x ? 1.0f : 0.0f;          // y-lanes: identity rotation
    float cf[4], sf[4];
    #pragma unroll
    for (int j = 0; j < 4; j++)
        sincosf(step * fr[j], &sf[j], &cf[j]);

    #pragma unroll 1
    for (int it = 0; it < GROUPS_PER_WARP; it++) {
        unsigned g  = gw * GROUPS_PER_WARP + it;   // 0..32767
        unsigned p0 = g * ROWS_PER_WARP;           // base position
        unsigned y  = p0 >> 9;
        unsigned x0 = p0 & 511u;

        float pos = is_x ? (float)x0 : (float)y;

        float c[4], s[4];
        #pragma unroll
        for (int j = 0; j < 4; j++)
            sincosf(pos * fr[j], &s[j], &c[j]);

        float4* rowc = out + (size_t)p0 * 32u + q;        // cos half
        float4* rows = rowc + (size_t)RP_HW * 32u;        // sin half

        #pragma unroll
        for (int i = 0; i < ROWS_PER_WARP; i++) {
            float4 vc, vs;
            vc.x = c[0]; vc.y = c[1]; vc.z = c[2]; vc.w = c[3];
            vs.x = s[0]; vs.y = s[1]; vs.z = s[2]; vs.w = s[3];
            __stcs(rowc + (size_t)i * 32u, vc);   // 512B/warp, cos stream
            __stcs(rows + (size_t)i * 32u, vs);   // 512B/warp, sin stream

            if (i < ROWS_PER_WARP - 1) {
                #pragma unroll
                for (int j = 0; j < 4; j++) {
                    float cn = fmaf(c[j], cf[j], -s[j] * sf[j]);
                    float sn = fmaf(s[j], cf[j],  c[j] * sf[j]);
                    c[j] = cn;
                    s[j] = sn;
                }
            }
        }
    }
}

extern "C" void kernel_launch(void* const* d_in, const int* in_sizes, int n_in,
                              void* d_out, int out_size) {
    const float* inv_freq_x = (const float*)d_in[1];
    const float* inv_freq_y = (const float*)d_in[2];
    float4* out = (float4*)d_out;

    // Single wave: 1024 blocks x 256 threads; each warp does 4 groups x 8 rows.
    rope2d_fused<<<1024, 256>>>(out, inv_freq_x, inv_freq_y);
}

// round 16
// speedup vs baseline: 1.0635x; 1.0635x over previous
#include <cuda_runtime.h>
#include <cuda_bf16.h>
#include <cstdint>

// RoPE2D encoder: output = [cos_2d (HW x 128) ; sin_2d (HW x 128)], fp32.
// H = W = 512, DIM = 128. Channels [0,64) depend only on x, [64,128) only on y.
// CONVERGED FINAL (15-round session): all well-occupied variants ride the
// ~6300 B/cyc LTS write-path chip cap (268.4 MB -> ~38.5us kernel floor);
// this variant is selected for minimum instructions/byte (issue 30% vs 65%
// for a which-split layout), making it most robust when DVFS throttling makes
// clock-domain issue/L1 the limiter (observed on this chip).
// Each warp: 8 consecutive positions (same y), stores BOTH cos and sin rows
// from one sincosf set + angle-addition recurrence. Lane q = float4 chunk:
// q<16 x-half (rotates by f per row), q>=16 y-half (identity rotation).
// Zero table loads; one 16B inv_freq read per thread; streaming STG.128.

#define RP_H 512
#define RP_W 512
#define RP_HW (RP_H * RP_W)
#define ROWS_PER_WARP 8

__global__ void __launch_bounds__(256) rope2d_fused(float4* __restrict__ out,
                                                    const float* __restrict__ inv_freq_x,
                                                    const float* __restrict__ inv_freq_y) {
    unsigned warp_in_block = threadIdx.x >> 5;
    unsigned q             = threadIdx.x & 31u;
    unsigned gw  = blockIdx.x * 8u + warp_in_block;   // 0..32767
    unsigned p0  = gw * ROWS_PER_WARP;                // base position
    unsigned y   = p0 >> 9;
    unsigned x0  = p0 & 511u;

    bool is_x = (q < 16u);

    // channels 4*(q mod 16)+j ; freq index mod 32 -> aligned float4 at q&7.
    const float4* tf = reinterpret_cast<const float4*>(is_x ? inv_freq_x : inv_freq_y);
    float4 f4 = __ldg(tf + (q & 7u));
    float fr[4] = {f4.x, f4.y, f4.z, f4.w};

    float pos  = is_x ? (float)x0 : (float)y;
    float step = is_x ? 1.0f : 0.0f;          // y-lanes: identity rotation

    float c[4], s[4], cf[4], sf[4];
    #pragma unroll
    for (int j = 0; j < 4; j++) {
        sincosf(pos * fr[j], &s[j], &c[j]);
        sincosf(step * fr[j], &sf[j], &cf[j]);
    }

    float4* rowc = out + (size_t)p0 * 32u + q;                    // cos half
    float4* rows = rowc + (size_t)RP_HW * 32u;                    // sin half

    #pragma unroll
    for (int i = 0; i < ROWS_PER_WARP; i++) {
        float4 vc, vs;
        vc.x = c[0]; vc.y = c[1]; vc.z = c[2]; vc.w = c[3];
        vs.x = s[0]; vs.y = s[1]; vs.z = s[2]; vs.w = s[3];
        __stcs(rowc + (size_t)i * 32u, vc);   // 512B/warp, cos stream
        __stcs(rows + (size_t)i * 32u, vs);   // 512B/warp, sin stream

        if (i < ROWS_PER_WARP - 1) {
            #pragma unroll
            for (int j = 0; j < 4; j++) {
                float cn = fmaf(c[j], cf[j], -s[j] * sf[j]);
                float sn = fmaf(s[j], cf[j],  c[j] * sf[j]);
                c[j] = cn;
                s[j] = sn;
            }
        }
    }
}

extern "C" void kernel_launch(void* const* d_in, const int* in_sizes, int n_in,
                              void* d_out, int out_size) {
    const float* inv_freq_x = (const float*)d_in[1];
    const float* inv_freq_y = (const float*)d_in[2];
    float4* out = (float4*)d_out;

    // 32768 warps x 8 positions = 262144 positions; 8 warps/block -> 4096 blocks
    rope2d_fused<<<4096, 256>>>(out, inv_freq_x, inv_freq_y);
}

// round 17
// speedup vs baseline: 1.0942x; 1.0288x over previous
#include <cuda_runtime.h>
#include <cuda_bf16.h>
#include <cstdint>

// RoPE2D encoder: output = [cos_2d (HW x 128) ; sin_2d (HW x 128)], fp32.
// H = W = 512, DIM = 128. Channels [0,64) depend only on x, [64,128) only on y.
// CONVERGED FINAL (17-round session). Which-split layout: warp = fixed half
// (cos or sin) + 8 consecutive positions (same y) -> ONE monotone store
// stream per warp (measured ~0.7us faster kernels than dual-emit layouts,
// which split stores across L2 regions 128MB apart). Session-best kernel
// time for this exact code: 38.24us = 7.0 TB/s = the LTS write-path cap.
// Lane q = float4 chunk: q<16 x-half (rotates by f per row), q>=16 y-half
// (identity rotation). sincosf prologue; angle-addition recurrence with c/s
// pre-swapped by `which` so the store loop is pure FFMA + STG.128.

#define RP_H 512
#define RP_W 512
#define RP_HW (RP_H * RP_W)
#define ROWS_PER_WARP 8

__global__ void __launch_bounds__(256) rope2d_fused(float4* __restrict__ out,
                                                    const float* __restrict__ inv_freq_x,
                                                    const float* __restrict__ inv_freq_y) {
    unsigned warp_in_block = threadIdx.x >> 5;
    unsigned q             = threadIdx.x & 31u;
    unsigned gw    = blockIdx.x * 8u + warp_in_block;   // 0..65535
    unsigned which = gw >> 15;                          // 0 = cos, 1 = sin
    unsigned rp    = gw & 32767u;
    unsigned p0    = rp * ROWS_PER_WARP;
    unsigned y     = p0 >> 9;
    unsigned x0    = p0 & 511u;

    bool is_x = (q < 16u);

    // channels 4*(q mod 16)+j ; freq index mod 32 -> aligned float4 at q&7.
    const float4* tf = reinterpret_cast<const float4*>(is_x ? inv_freq_x : inv_freq_y);
    float4 f4 = __ldg(tf + (q & 7u));
    float fr[4] = {f4.x, f4.y, f4.z, f4.w};

    float pos  = is_x ? (float)x0 : (float)y;
    float step = is_x ? 1.0f : 0.0f;          // y-lanes: identity rotation

    // a[] = emitted value (cos or sin per `which`), b[] = companion.
    //   emit cos: a=cos,b=sin, sign=-1 ; emit sin: a=sin,b=cos, sign=+1
    //   a' = a*cf + sign*b*sf ; b' = b*cf - sign*a*sf   (sign folded into sf)
    float a[4], b[4], cf[4], sf[4];
    float sign = which ? 1.0f : -1.0f;
    #pragma unroll
    for (int j = 0; j < 4; j++) {
        float cc, ss;
        sincosf(pos * fr[j], &ss, &cc);
        a[j] = which ? ss : cc;
        b[j] = which ? cc : ss;
        sincosf(step * fr[j], &sf[j], &cf[j]);
        sf[j] *= sign;                      // fold sign into sf once
    }

    float4* row = out + (size_t)which * (RP_HW * 32u) + (size_t)p0 * 32u + q;

    #pragma unroll
    for (int i = 0; i < ROWS_PER_WARP; i++) {
        float4 val;
        val.x = a[0]; val.y = a[1]; val.z = a[2]; val.w = a[3];
        __stcs(row + (size_t)i * 32u, val);   // streaming 512B/warp store

        if (i < ROWS_PER_WARP - 1) {
            #pragma unroll
            for (int j = 0; j < 4; j++) {
                float an = fmaf(a[j], cf[j],  b[j] * sf[j]);
                float bn = fmaf(b[j], cf[j], -a[j] * sf[j]);
                a[j] = an;
                b[j] = bn;
            }
        }
    }
}

extern "C" void kernel_launch(void* const* d_in, const int* in_sizes, int n_in,
                              void* d_out, int out_size) {
    const float* inv_freq_x = (const float*)d_in[1];
    const float* inv_freq_y = (const float*)d_in[2];
    float4* out = (float4*)d_out;

    // 65536 warps = 2 (which) x 32768 row-groups; 8 warps/block -> 8192 blocks
    rope2d_fused<<<8192, 256>>>(out, inv_freq_x, inv_freq_y);
}